// round 11
// baseline (speedup 1.0000x reference)
#include <cuda_runtime.h>
#include <cuda_bf16.h>
#include <cstdint>

// Problem constants
#define N_TOT 4096
#define D1    4096
#define D2    2048
#define NTV   32            // 128-row/col blocks per dim
#define NTILES 528          // upper-triangle tiles (I <= J)
#define BK    64            // k-tile

// SMEM per CTA: 3 stages A (3x16KB) | 3 stages B (3x16KB) | reduction scratch
#define SM_ASTAGE 16384
#define SM_BSTAGE 16384
#define SM_B_OFF  49152
#define SM_RED    98304
#define SMEM_TOTAL (98304 + 128)

// ---------------- device scratch ----------------
__device__ __nv_bfloat16 g_t1[(size_t)N_TOT * D1];   // 32 MB
__device__ __nv_bfloat16 g_t2[(size_t)N_TOT * D2];   // 16 MB
__device__ float g_sq1[N_TOT];
__device__ float g_sq2[N_TOT];
__device__ float g_pcs1[(size_t)1024 * D1];          // 16 MB
__device__ float g_pcs2[(size_t)1024 * D2];          // 8 MB
__device__ float g_colsum1[D1];
__device__ float g_colsum2[D2];
__device__ float g_c[2];
__device__ float g_partials[NTILES];
__device__ float g_kk[(size_t)NTILES * 16384];       // 34.6 MB k1 scratch

// ---------------- helpers ----------------
__device__ __forceinline__ float ex2f(float x) {
    float y; asm("ex2.approx.ftz.f32 %0, %1;" : "=f"(y) : "f"(x)); return y;
}
// sum_{i=0..4} exp(-t/2^i) = y + y^2 + y^4 + y^8 + y^16, y = exp(-t/16)
__device__ __forceinline__ float kern5b(float l2, float c16) {
    float y = ex2f(-fmaxf(l2, 0.0f) * c16);
    float y2 = y * y, y4 = y2 * y2, y8 = y4 * y4, y16 = y8 * y8;
    return y + y2 + y4 + y8 + y16;
}
__device__ __forceinline__ void cpa16(uint32_t s, const void* g) {
    asm volatile("cp.async.cg.shared.global [%0], [%1], 16;" :: "r"(s), "l"(g));
}
__device__ __forceinline__ void ldsm4(uint32_t* r, uint32_t addr) {
    asm volatile("ldmatrix.sync.aligned.m8n8.x4.shared.b16 {%0,%1,%2,%3}, [%4];"
        : "=r"(r[0]), "=r"(r[1]), "=r"(r[2]), "=r"(r[3]) : "r"(addr));
}
__device__ __forceinline__ void mma16816(float* d, const uint32_t* a, const uint32_t* b) {
    asm volatile(
        "mma.sync.aligned.m16n8k16.row.col.f32.bf16.bf16.f32 "
        "{%0,%1,%2,%3}, {%4,%5,%6,%7}, {%8,%9}, {%0,%1,%2,%3};"
        : "+f"(d[0]), "+f"(d[1]), "+f"(d[2]), "+f"(d[3])
        : "r"(a[0]), "r"(a[1]), "r"(a[2]), "r"(a[3]), "r"(b[0]), "r"(b[1]));
}

// ---------------- pre-pass 1: convert + row sq-norms + col partial sums ----------------
__global__ void kprep(const float* __restrict__ z1s, const float* __restrict__ z1t,
                      const float* __restrict__ z2s, const float* __restrict__ z2t) {
    int bid = blockIdx.x, tid = threadIdx.x;
    int lane = tid & 31, wid = tid >> 5;
    __shared__ float sred1[4][8];
    __shared__ float sred2[4][8];
    float4 ca1[4], ca2[2];
    #pragma unroll
    for (int s = 0; s < 4; s++) ca1[s] = make_float4(0.f, 0.f, 0.f, 0.f);
    #pragma unroll
    for (int s = 0; s < 2; s++) ca2[s] = make_float4(0.f, 0.f, 0.f, 0.f);

    for (int r4 = 0; r4 < 4; r4++) {
        int r = bid * 4 + r4;
        const float4* s1 = (const float4*)((r < 2048) ? z1s + (size_t)r * D1
                                                      : z1t + (size_t)(r - 2048) * D1);
        float sq = 0.0f;
        #pragma unroll
        for (int s = 0; s < 4; s++) {
            float4 v = s1[tid + 256 * s];
            __nv_bfloat162 h0 = {__float2bfloat16(v.x), __float2bfloat16(v.y)};
            __nv_bfloat162 h1 = {__float2bfloat16(v.z), __float2bfloat16(v.w)};
            uint2 pk = {*(uint32_t*)&h0, *(uint32_t*)&h1};
            *(uint2*)(g_t1 + (size_t)r * D1 + 4 * (tid + 256 * s)) = pk;
            sq += v.x * v.x + v.y * v.y + v.z * v.z + v.w * v.w;
            ca1[s].x += v.x; ca1[s].y += v.y; ca1[s].z += v.z; ca1[s].w += v.w;
        }
        #pragma unroll
        for (int o = 16; o; o >>= 1) sq += __shfl_xor_sync(0xffffffffu, sq, o);
        if (lane == 0) sred1[r4][wid] = sq;

        const float4* s2 = (const float4*)((r < 2048) ? z2s + (size_t)r * D2
                                                      : z2t + (size_t)(r - 2048) * D2);
        sq = 0.0f;
        #pragma unroll
        for (int s = 0; s < 2; s++) {
            float4 v = s2[tid + 256 * s];
            __nv_bfloat162 h0 = {__float2bfloat16(v.x), __float2bfloat16(v.y)};
            __nv_bfloat162 h1 = {__float2bfloat16(v.z), __float2bfloat16(v.w)};
            uint2 pk = {*(uint32_t*)&h0, *(uint32_t*)&h1};
            *(uint2*)(g_t2 + (size_t)r * D2 + 4 * (tid + 256 * s)) = pk;
            sq += v.x * v.x + v.y * v.y + v.z * v.z + v.w * v.w;
            ca2[s].x += v.x; ca2[s].y += v.y; ca2[s].z += v.z; ca2[s].w += v.w;
        }
        #pragma unroll
        for (int o = 16; o; o >>= 1) sq += __shfl_xor_sync(0xffffffffu, sq, o);
        if (lane == 0) sred2[r4][wid] = sq;
    }
    #pragma unroll
    for (int s = 0; s < 4; s++)
        *(float4*)&g_pcs1[(size_t)bid * D1 + 1024 * s + 4 * tid] = ca1[s];
    #pragma unroll
    for (int s = 0; s < 2; s++)
        *(float4*)&g_pcs2[(size_t)bid * D2 + 1024 * s + 4 * tid] = ca2[s];
    __syncthreads();
    if (tid < 4) {
        float s = 0.0f;
        #pragma unroll
        for (int w = 0; w < 8; w++) s += sred1[tid][w];
        g_sq1[bid * 4 + tid] = s;
    } else if (tid < 8) {
        float s = 0.0f;
        #pragma unroll
        for (int w = 0; w < 8; w++) s += sred2[tid - 4][w];
        g_sq2[bid * 4 + tid - 4] = s;
    }
}

// ---------------- pre-pass 2: reduce col partial sums ----------------
__global__ void kcol2() {
    int tid = threadIdx.x;
    if (blockIdx.x < 16) {
        int j = blockIdx.x * 256 + tid;
        float s = 0.0f;
        for (int k = 0; k < 1024; k++) s += g_pcs1[(size_t)k * D1 + j];
        g_colsum1[j] = s;
    } else {
        int j = (blockIdx.x - 16) * 256 + tid;
        float s = 0.0f;
        for (int k = 0; k < 1024; k++) s += g_pcs2[(size_t)k * D2 + j];
        g_colsum2[j] = s;
    }
}

// ---------------- pre-pass 3: bandwidth constants ----------------
__global__ void kconst() {
    int tid = threadIdx.x;
    __shared__ double sh[512];

    double ssq = 0.0, ss = 0.0;
    for (int j = tid; j < D1; j += 256) { double v = (double)g_colsum1[j]; ss += v * v; }
    for (int j = tid; j < N_TOT; j += 256) ssq += (double)g_sq1[j];
    sh[tid] = ssq; sh[256 + tid] = ss; __syncthreads();
    for (int s = 128; s; s >>= 1) {
        if (tid < s) { sh[tid] += sh[tid + s]; sh[256 + tid] += sh[256 + tid + s]; }
        __syncthreads();
    }
    if (tid == 0) {
        double n = (double)N_TOT;
        double suml2 = 2.0 * n * sh[0] - 2.0 * sh[256];
        double bw = suml2 / (n * n - n) / 4.0;
        g_c[0] = (float)(1.4426950408889634 / bw);
    }
    __syncthreads();

    ssq = 0.0; ss = 0.0;
    for (int j = tid; j < D2; j += 256) { double v = (double)g_colsum2[j]; ss += v * v; }
    for (int j = tid; j < N_TOT; j += 256) ssq += (double)g_sq2[j];
    sh[tid] = ssq; sh[256 + tid] = ss; __syncthreads();
    for (int s = 128; s; s >>= 1) {
        if (tid < s) { sh[tid] += sh[tid + s]; sh[256 + tid] += sh[256 + tid + s]; }
        __syncthreads();
    }
    if (tid == 0) {
        double n = (double)N_TOT;
        double suml2 = 2.0 * n * sh[0] - 2.0 * sh[256];
        double bw = suml2 / (n * n - n) / 4.0;
        g_c[1] = (float)(1.4426950408889634 / bw);
    }
}

// ---------------- main fused kernel: 128x128 CTA, 8 warps, 2 CTAs/SM ----------------
__device__ __forceinline__ void load_tiles(uint32_t sb, int stage,
        const __nv_bfloat16* A, const __nv_bfloat16* B, int ld, int k0, int tid) {
    uint32_t sA = sb + (uint32_t)stage * SM_ASTAGE;
    uint32_t sB = sb + SM_B_OFF + (uint32_t)stage * SM_BSTAGE;
    #pragma unroll
    for (int v = 0; v < 4; v++) {               // A: 128x64 = 1024 x 16B
        int chunk = tid + v * 256;
        int row = chunk >> 3, c = chunk & 7;
        uint32_t off = (uint32_t)(row * 128 + ((c ^ (row & 7)) << 4));   // SW128
        cpa16(sA + off, A + (size_t)row * ld + k0 + c * 8);
    }
    #pragma unroll
    for (int v = 0; v < 4; v++) {               // B: 128x64 = 1024 x 16B
        int chunk = tid + v * 256;
        int row = chunk >> 3, c = chunk & 7;
        uint32_t off = (uint32_t)(row * 128 + ((c ^ (row & 7)) << 4));
        cpa16(sB + off, B + (size_t)row * ld + k0 + c * 8);
    }
}

__device__ __forceinline__ void compute_stage(uint32_t sA, uint32_t sB,
        float acc[4][4][4], int lane, int wm, int wn) {
    #pragma unroll
    for (int s16 = 0; s16 < 4; s16++) {
        uint32_t a[4][4], b[2][4];
        #pragma unroll
        for (int mt = 0; mt < 4; mt++) {
            int row = wm * 64 + mt * 16 + (lane & 15);
            int ch  = 2 * s16 + (lane >> 4);
            ldsm4(a[mt], sA + (uint32_t)(row * 128 + ((ch ^ (row & 7)) << 4)));
        }
        #pragma unroll
        for (int p = 0; p < 2; p++) {
            int g = lane >> 3;
            int row = wn * 32 + p * 16 + ((g >> 1) << 3) + (lane & 7);
            int ch  = 2 * s16 + (g & 1);
            ldsm4(b[p], sB + (uint32_t)(row * 128 + ((ch ^ (row & 7)) << 4)));
        }
        #pragma unroll
        for (int mt = 0; mt < 4; mt++)
            #pragma unroll
            for (int nt = 0; nt < 4; nt++)
                mma16816(acc[mt][nt], a[mt], &b[nt >> 1][(nt & 1) * 2]);
    }
}

__device__ void run_gemm(const __nv_bfloat16* A, const __nv_bfloat16* B, int ld,
        int nsteps, float acc[4][4][4], uint32_t sb, int tid, int lane, int wm, int wn) {
    asm volatile("cp.async.wait_group 0;");     // prior phase fully drained
    __syncthreads();
    #pragma unroll
    for (int s = 0; s < 2; s++) {
        load_tiles(sb, s, A, B, ld, s * BK, tid);
        asm volatile("cp.async.commit_group;");
    }
    for (int s = 0; s < nsteps; s++) {
        asm volatile("cp.async.wait_group 1;");
        __syncthreads();
        if (s + 2 < nsteps)
            load_tiles(sb, (s + 2) % 3, A, B, ld, (s + 2) * BK, tid);
        asm volatile("cp.async.commit_group;"); // 1 group/iter invariant
        compute_stage(sb + (uint32_t)(s % 3) * SM_ASTAGE,
                      sb + SM_B_OFF + (uint32_t)(s % 3) * SM_BSTAGE,
                      acc, lane, wm, wn);
    }
}

__global__ __launch_bounds__(256, 2) void kmain() {
    extern __shared__ __align__(16) char smem[];
    uint32_t sb = (uint32_t)__cvta_generic_to_shared(smem);
    int tid = threadIdx.x, lane = tid & 31, wid = tid >> 5;
    int wm = wid >> 2, wn = wid & 3;    // 2 x 4 warp grid, warp tile 64x32

    // upper-triangle tile mapping: (I,J), J >= I
    int rem = blockIdx.x, I = 0;
    while (rem >= NTV - I) { rem -= NTV - I; I++; }
    int J = I + rem;

    float acc[4][4][4];
    #pragma unroll
    for (int mt = 0; mt < 4; mt++)
        #pragma unroll
        for (int nt = 0; nt < 4; nt++)
            #pragma unroll
            for (int r = 0; r < 4; r++) acc[mt][nt][r] = 0.0f;

    // ---- phase 1: G1 over total1 ----
    run_gemm(g_t1 + (size_t)(I * 128) * D1, g_t1 + (size_t)(J * 128) * D1,
             D1, D1 / BK, acc, sb, tid, lane, wm, wn);

    {
        float c116 = g_c[0] * 0.0625f;
        float sqi[4][2], sqj[4][2];
        #pragma unroll
        for (int mt = 0; mt < 4; mt++) {
            int ib = I * 128 + wm * 64 + mt * 16 + (lane >> 2);
            sqi[mt][0] = g_sq1[ib];
            sqi[mt][1] = g_sq1[ib + 8];
        }
        #pragma unroll
        for (int nt = 0; nt < 4; nt++) {
            int jb = J * 128 + wn * 32 + nt * 8 + ((lane & 3) << 1);
            sqj[nt][0] = g_sq1[jb];
            sqj[nt][1] = g_sq1[jb + 1];
        }
        float* kkb = g_kk + (size_t)blockIdx.x * 16384 + tid * 64;
        #pragma unroll
        for (int mt = 0; mt < 4; mt++)
            #pragma unroll
            for (int nt = 0; nt < 4; nt++) {
                float4 kv;
                float* kp = (float*)&kv;
                #pragma unroll
                for (int r = 0; r < 4; r++) {
                    float l2 = sqi[mt][r >> 1] + sqj[nt][r & 1] - 2.0f * acc[mt][nt][r];
                    kp[r] = kern5b(l2, c116);
                    acc[mt][nt][r] = 0.0f;
                }
                *(float4*)(kkb + mt * 16 + nt * 4) = kv;
            }
    }

    // ---- phase 2: G2 over total2 ----
    run_gemm(g_t2 + (size_t)(I * 128) * D2, g_t2 + (size_t)(J * 128) * D2,
             D2, D2 / BK, acc, sb, tid, lane, wm, wn);

    float part = 0.0f;
    {
        float c216 = g_c[1] * 0.0625f;
        float sqi[4][2], sqj[4][2];
        #pragma unroll
        for (int mt = 0; mt < 4; mt++) {
            int ib = I * 128 + wm * 64 + mt * 16 + (lane >> 2);
            sqi[mt][0] = g_sq2[ib];
            sqi[mt][1] = g_sq2[ib + 8];
        }
        #pragma unroll
        for (int nt = 0; nt < 4; nt++) {
            int jb = J * 128 + wn * 32 + nt * 8 + ((lane & 3) << 1);
            sqj[nt][0] = g_sq2[jb];
            sqj[nt][1] = g_sq2[jb + 1];
        }
        const float PC = 1.0f / (2048.0f * 2047.0f);
        const float QC = 1.0f / (2048.0f * 2048.0f);
        const float* kkb = g_kk + (size_t)blockIdx.x * 16384 + tid * 64;
        #pragma unroll
        for (int mt = 0; mt < 4; mt++)
            #pragma unroll
            for (int nt = 0; nt < 4; nt++) {
                float4 kv = *(const float4*)(kkb + mt * 16 + nt * 4);
                const float* kp = (const float*)&kv;
                #pragma unroll
                for (int r = 0; r < 4; r++) {
                    int i = I * 128 + wm * 64 + mt * 16 + (lane >> 2) + ((r >> 1) << 3);
                    int j = J * 128 + wn * 32 + nt * 8 + ((lane & 3) << 1) + (r & 1);
                    float l2 = sqi[mt][r >> 1] + sqj[nt][r & 1] - 2.0f * acc[mt][nt][r];
                    float k2v = kern5b(l2, c216);
                    // strictly-upper mask, x2 symmetry, +/- index-matrix coefficient
                    float coef = (i < j) ? 2.0f * (((i >> 11) == (j >> 11)) ? PC : -QC)
                                         : 0.0f;
                    part += kp[r] * k2v * coef;
                }
            }
    }

    // deterministic CTA reduction
    #pragma unroll
    for (int o = 16; o; o >>= 1) part += __shfl_xor_sync(0xffffffffu, part, o);
    float* red = (float*)(smem + SM_RED);
    __syncthreads();
    if (lane == 0) red[wid] = part;
    __syncthreads();
    if (tid == 0) {
        float s = 0.0f;
        #pragma unroll
        for (int w = 0; w < 8; w++) s += red[w];
        g_partials[blockIdx.x] = s;
    }
}

// ---------------- final deterministic reduction ----------------
__global__ void kred(float* out) {
    int tid = threadIdx.x;
    __shared__ double sh[256];
    double a = 0.0;
    for (int i = tid; i < NTILES; i += 256) a += (double)g_partials[i];
    sh[tid] = a; __syncthreads();
    for (int s = 128; s; s >>= 1) { if (tid < s) sh[tid] += sh[tid + s]; __syncthreads(); }
    if (tid == 0) out[0] = (float)(sh[0] + 2.0 / 2047.0);
}

// ---------------- launch ----------------
extern "C" void kernel_launch(void* const* d_in, const int* in_sizes, int n_in,
                              void* d_out, int out_size) {
    const float* z1s = (const float*)d_in[0];
    const float* z1t = (const float*)d_in[1];
    const float* z2s = (const float*)d_in[2];
    const float* z2t = (const float*)d_in[3];

    cudaFuncSetAttribute(kmain, cudaFuncAttributeMaxDynamicSharedMemorySize, SMEM_TOTAL);

    kprep<<<1024, 256>>>(z1s, z1t, z2s, z2t);
    kcol2<<<24, 256>>>();
    kconst<<<1, 256>>>();
    kmain<<<NTILES, 256, SMEM_TOTAL>>>();
    kred<<<1, 256>>>((float*)d_out);
}